// round 15
// baseline (speedup 1.0000x reference)
#include <cuda_runtime.h>
#include <cuda_fp16.h>
#include <math.h>
#include <stdint.h>

#define T 2048
#define D 2048
#define E 8
#define F 1408
#define N1 (2 * F)   // interleaved gate/up N dimension = 2816

// ---------------- scratch (device globals; no allocation allowed) ----------
__device__ __align__(16) __half g_Wgu[(size_t)E * D * N1];  // [e][k=d][n=2f+s]
__device__ __align__(16) __half g_Wd [(size_t)E * F * D];   // [e][k=f][n=d]
__device__ __align__(16) __half g_X  [(size_t)E * T * D];   // gathered fp16 tokens
__device__ __align__(16) __half g_H  [(size_t)E * T * F];   // silu(g)*u fp16
__device__ int   g_cnt[E];
__device__ int   g_tok[E * T];
__device__ float g_wt [E * T];
__device__ int   g_dst[T * 2];

// ---------------- streams/events: created ONCE at process init -------------
static cudaStream_t s_cv, s_e[E];
static cudaEvent_t  ev_fork, ev_route, ev_gu[E], ev_d[E], ev_done[E];
static struct _StreamInit {
    _StreamInit() {
        cudaStreamCreateWithFlags(&s_cv, cudaStreamNonBlocking);
        cudaEventCreateWithFlags(&ev_fork,  cudaEventDisableTiming);
        cudaEventCreateWithFlags(&ev_route, cudaEventDisableTiming);
        for (int e = 0; e < E; e++) {
            cudaStreamCreateWithFlags(&s_e[e], cudaStreamNonBlocking);
            cudaEventCreateWithFlags(&ev_gu[e],   cudaEventDisableTiming);
            cudaEventCreateWithFlags(&ev_d[e],    cudaEventDisableTiming);
            cudaEventCreateWithFlags(&ev_done[e], cudaEventDisableTiming);
        }
    }
} _stream_init;

// ---------------- helpers ---------------------------------------------------
__global__ void zero_cnt_kernel() {
    if (threadIdx.x < E) g_cnt[threadIdx.x] = 0;
}

// per-expert gate+up convert with column interleave
__global__ void convert_gu_kernel(const float4* __restrict__ wg,
                                  const float4* __restrict__ wu, int e) {
    const int n4 = D * F / 4;
    const size_t base = (size_t)e * n4;
    uint4* dst = (uint4*)g_Wgu + base;
    const float4* sg = wg + base;
    const float4* su = wu + base;
    for (int i = blockIdx.x * blockDim.x + threadIdx.x; i < n4;
         i += gridDim.x * blockDim.x) {
        float4 g = sg[i];
        float4 u = su[i];
        __half2 h[4];
        h[0] = __floats2half2_rn(g.x, u.x);
        h[1] = __floats2half2_rn(g.y, u.y);
        h[2] = __floats2half2_rn(g.z, u.z);
        h[3] = __floats2half2_rn(g.w, u.w);
        dst[i] = *(uint4*)h;
    }
}

// per-expert down convert
__global__ void convert_d_kernel(const float4* __restrict__ wd, int e) {
    const int n4 = F * D / 4;
    const size_t base = (size_t)e * n4;
    __half2* dst = (__half2*)g_Wd + base * 2;
    const float4* src = wd + base;
    for (int i = blockIdx.x * blockDim.x + threadIdx.x; i < n4;
         i += gridDim.x * blockDim.x) {
        float4 v = src[i];
        dst[2 * i + 0] = __floats2half2_rn(v.x, v.y);
        dst[2 * i + 1] = __floats2half2_rn(v.z, v.w);
    }
}

// ---------------- router: 4 warps per token, 2 tokens per block -------------
__global__ void router_kernel(const float4* __restrict__ x4,
                              const float* __restrict__ gw) {
    __shared__ float red[2][4][E];
    int tid = threadIdx.x;
    int warp = tid >> 5, lane = tid & 31;
    int tl = warp >> 2;
    int q  = warp & 3;
    int t = blockIdx.x * 2 + tl;

    float acc[E];
#pragma unroll
    for (int e = 0; e < E; e++) acc[e] = 0.f;
    const float4* xr = x4 + (size_t)t * (D / 4) + q * (D / 16);
    const float4* gw4 = (const float4*)gw;
#pragma unroll
    for (int i = lane; i < D / 16; i += 32) {
        float4 v = xr[i];
#pragma unroll
        for (int e = 0; e < E; e++) {
            float4 g = gw4[(size_t)e * (D / 4) + q * (D / 16) + i];
            acc[e] += v.x * g.x + v.y * g.y + v.z * g.z + v.w * g.w;
        }
    }
#pragma unroll
    for (int e = 0; e < E; e++)
#pragma unroll
        for (int o = 16; o; o >>= 1)
            acc[e] += __shfl_xor_sync(0xffffffffu, acc[e], o);
    if (lane == 0)
#pragma unroll
        for (int e = 0; e < E; e++) red[tl][q][e] = acc[e];
    __syncthreads();

    if ((warp & 3) == 0 && lane == 0) {
        float l[E], m = -1e30f;
#pragma unroll
        for (int e = 0; e < E; e++) {
            l[e] = red[tl][0][e] + red[tl][1][e] + red[tl][2][e] + red[tl][3][e];
            m = fmaxf(m, l[e]);
        }
        float p[E], sum = 0.f;
#pragma unroll
        for (int e = 0; e < E; e++) { p[e] = expf(l[e] - m); sum += p[e]; }
        float inv = 1.f / sum;
#pragma unroll
        for (int e = 0; e < E; e++) p[e] *= inv;
        int i1 = 0;
#pragma unroll
        for (int e = 1; e < E; e++) if (p[e] > p[i1]) i1 = e;
        int i2 = -1;
#pragma unroll
        for (int e = 0; e < E; e++)
            if (e != i1 && (i2 < 0 || p[e] > p[i2])) i2 = e;
        int r1 = atomicAdd(&g_cnt[i1], 1);
        g_tok[i1 * T + r1] = t;  g_wt[i1 * T + r1] = p[i1];
        g_dst[t * 2 + 0] = i1 * T + r1;
        int r2 = atomicAdd(&g_cnt[i2], 1);
        g_tok[i2 * T + r2] = t;  g_wt[i2 * T + r2] = p[i2];
        g_dst[t * 2 + 1] = i2 * T + r2;
    }
}

// ---------------- gather: exact slots ---------------------------------------
__global__ void gather_kernel(const float4* __restrict__ x4) {
    int t = blockIdx.x;
    int slot = g_dst[t * 2 + blockIdx.y];
    const float4* src = x4 + (size_t)t * (D / 4);
    __half2* dst = (__half2*)(g_X + (size_t)slot * D);
    for (int i = threadIdx.x; i < D / 4; i += 128) {
        float4 v = src[i];
        dst[2 * i + 0] = __floats2half2_rn(v.x, v.y);
        dst[2 * i + 1] = __floats2half2_rn(v.z, v.w);
    }
}

// ---------------- PTX primitives --------------------------------------------
__device__ __forceinline__ unsigned smem_u32(const void* p) {
    return (unsigned)__cvta_generic_to_shared(p);
}
__device__ __forceinline__ void cp16(void* dst, const void* src) {
    asm volatile("cp.async.cg.shared.global [%0], [%1], 16;\n"
                 :: "r"(smem_u32(dst)), "l"(src));
}
__device__ __forceinline__ void cp_commit() {
    asm volatile("cp.async.commit_group;\n");
}
template <int N>
__device__ __forceinline__ void cp_wait() {
    asm volatile("cp.async.wait_group %0;\n" :: "n"(N));
}
__device__ __forceinline__ void ldsm_x4(unsigned& r0, unsigned& r1,
                                        unsigned& r2, unsigned& r3,
                                        const void* p) {
    asm volatile("ldmatrix.sync.aligned.m8n8.x4.shared.b16 {%0,%1,%2,%3}, [%4];\n"
                 : "=r"(r0), "=r"(r1), "=r"(r2), "=r"(r3) : "r"(smem_u32(p)));
}
__device__ __forceinline__ void ldsm_x4t(unsigned& r0, unsigned& r1,
                                         unsigned& r2, unsigned& r3,
                                         const void* p) {
    asm volatile("ldmatrix.sync.aligned.m8n8.x4.trans.shared.b16 {%0,%1,%2,%3}, [%4];\n"
                 : "=r"(r0), "=r"(r1), "=r"(r2), "=r"(r3) : "r"(smem_u32(p)));
}
__device__ __forceinline__ void mma16816(float* c, const unsigned* a,
                                         const unsigned* b) {
    asm volatile(
        "mma.sync.aligned.m16n8k16.row.col.f32.f16.f16.f32 "
        "{%0,%1,%2,%3}, {%4,%5,%6,%7}, {%8,%9}, {%0,%1,%2,%3};\n"
        : "+f"(c[0]), "+f"(c[1]), "+f"(c[2]), "+f"(c[3])
        : "r"(a[0]), "r"(a[1]), "r"(a[2]), "r"(a[3]), "r"(b[0]), "r"(b[1]));
}

// ---------------- tiled GEMM: 128(M) x 256(N) x 32(K), 512 threads ----------
// A tile: 128 rows x 32 halfs = 512 x 16B chunks; phys = row*4  + (ch ^ ((row>>1)&3))
// B tile:  32 rows x 256 halfs = 1024 chunks;     phys = row*32 + (ch ^ (row&7))
// Stage = A 8KB + B 16KB = 24KB; 3 stages = 72KB dynamic smem; 1 CTA/SM.
// Warp layout (16 warps): wm = (warp>>2)*32 (mi=2 of 16), wn = (warp&3)*64 (ni=8 of 8).
#define BM 128
#define BN 256
#define BK 32
#define STG_U4 1536                    // uint4 per stage (A 512 + B 1024)
#define SMEM_TOTAL (3 * STG_U4 * 16)   // 73728 bytes

#define GEMM_LOAD_TILE(As, Bs, Aptr, ldA, Bptr, ldB, kk0)                      \
    {                                                                          \
        {                                                                      \
            int row = tid >> 2, ch = tid & 3;                                  \
            cp16(&(As)[(row << 2) + (ch ^ ((row >> 1) & 3))],                  \
                 Aptr + (size_t)row * (ldA) + (kk0) + ch * 8);                 \
        }                                                                      \
        _Pragma("unroll")                                                      \
        for (int c = tid; c < 1024; c += 512) {                                \
            int row = c >> 5, ch = c & 31;                                     \
            cp16(&(Bs)[(row << 5) + (ch ^ (row & 7))],                         \
                 Bptr + (size_t)((kk0) + row) * (ldB) + n0 + ch * 8);          \
        }                                                                      \
        cp_commit();                                                           \
    }

#define GEMM_COMPUTE_STAGE(As, Bs)                                             \
    {                                                                          \
        _Pragma("unroll")                                                      \
        for (int ks = 0; ks < BK; ks += 16) {                                  \
            unsigned a[2][4], b[8][2];                                         \
            int l15 = lane & 15, l16 = lane >> 4;                              \
            int kch = (ks >> 3) + l16;                                         \
            _Pragma("unroll")                                                  \
            for (int mi = 0; mi < 2; mi++) {                                   \
                int row = wm + mi * 16 + l15;                                  \
                ldsm_x4(a[mi][0], a[mi][1], a[mi][2], a[mi][3],                \
                        &(As)[(row << 2) + (kch ^ ((row >> 1) & 3))]);         \
            }                                                                  \
            int brow = ks + l15;                                               \
            _Pragma("unroll")                                                  \
            for (int nj = 0; nj < 4; nj++) {                                   \
                int nch = ((wn + nj * 16) >> 3) + l16;                         \
                unsigned r0, r1, r2, r3;                                       \
                ldsm_x4t(r0, r1, r2, r3,                                       \
                         &(Bs)[(brow << 5) + (nch ^ (brow & 7))]);             \
                b[2 * nj][0] = r0; b[2 * nj][1] = r1;                          \
                b[2 * nj + 1][0] = r2; b[2 * nj + 1][1] = r3;                  \
            }                                                                  \
            _Pragma("unroll")                                                  \
            for (int mi = 0; mi < 2; mi++)                                     \
                _Pragma("unroll")                                              \
                for (int ni = 0; ni < 8; ni++)                                 \
                    mma16816(acc[mi][ni], a[mi], b[ni]);                       \
        }                                                                      \
    }

// 3-stage, ONE barrier per K-tile (R14-proven skeleton).
#define GEMM_MAINLOOP(Aptr, ldA, Bptr, ldB, NK)                                \
    GEMM_LOAD_TILE(SM_A(0), SM_B(0), Aptr, ldA, Bptr, ldB, 0)                  \
    GEMM_LOAD_TILE(SM_A(1), SM_B(1), Aptr, ldA, Bptr, ldB, BK)                 \
    {                                                                          \
        int scur = 0;                                                          \
        for (int kt = 0; kt < (NK); kt++) {                                    \
            if (kt + 1 < (NK)) cp_wait<1>();                                   \
            else               cp_wait<0>();                                   \
            __syncthreads();                                                   \
            if (kt + 2 < (NK)) {                                               \
                int sl = scur + 2; if (sl >= 3) sl -= 3;                       \
                GEMM_LOAD_TILE(SM_A(sl), SM_B(sl), Aptr, ldA, Bptr, ldB,       \
                               (kt + 2) * BK)                                  \
            }                                                                  \
            GEMM_COMPUTE_STAGE(SM_A(scur), SM_B(scur))                         \
            scur = (scur == 2) ? 0 : scur + 1;                                 \
        }                                                                      \
    }

#define SM_A(s) (smu + (s) * STG_U4)
#define SM_B(s) (smu + (s) * STG_U4 + 512)

// ---------------- GEMM1 (per expert): H = silu(X @ Wg) * (X @ Wu) -----------
__global__ __launch_bounds__(512, 1) void gemm1_kernel(int e) {
    extern __shared__ uint4 smu[];
    int cnt = g_cnt[e];
    int m0 = blockIdx.y * BM;
    if (m0 >= cnt) return;
    int n0 = blockIdx.x * BN;

    const __half* A = g_X   + ((size_t)e * T + m0) * D;
    const __half* B = g_Wgu + (size_t)e * D * N1;

    int tid = threadIdx.x;
    int warp = tid >> 5, lane = tid & 31;
    int wm = (warp >> 2) * 32;
    int wn = (warp & 3) * 64;
    int grp = lane >> 2, tig = lane & 3;

    float acc[2][8][4];
#pragma unroll
    for (int mi = 0; mi < 2; mi++)
#pragma unroll
        for (int ni = 0; ni < 8; ni++)
#pragma unroll
            for (int q = 0; q < 4; q++) acc[mi][ni][q] = 0.f;

    GEMM_MAINLOOP(A, D, B, N1, D / BK)

    __half* Hp = g_H + (size_t)e * T * F;
#pragma unroll
    for (int mi = 0; mi < 2; mi++) {
#pragma unroll
        for (int h = 0; h < 2; h++) {
            int grow = m0 + wm + mi * 16 + grp + h * 8;
            if (grow >= cnt) continue;
            __half* hrow = Hp + (size_t)grow * F;
#pragma unroll
            for (int ni = 0; ni < 8; ni++) {
                int ng = n0 + wn + ni * 8;
                int f = (ng >> 1) + tig;
                float g = acc[mi][ni][h * 2 + 0];
                float u = acc[mi][ni][h * 2 + 1];
                float hv = (g / (1.f + __expf(-g))) * u;
                hrow[f] = __float2half_rn(hv);
            }
        }
    }
}

// ---------------- GEMM2 (per expert): out += wt * (H @ Wd) ------------------
__global__ __launch_bounds__(512, 1) void gemm2_kernel(int e, float* __restrict__ out) {
    extern __shared__ uint4 smu[];
    int cnt = g_cnt[e];
    int m0 = blockIdx.y * BM;
    if (m0 >= cnt) return;
    int n0 = blockIdx.x * BN;

    const __half* A = g_H  + ((size_t)e * T + m0) * F;
    const __half* B = g_Wd + (size_t)e * F * D;

    int tid = threadIdx.x;
    int warp = tid >> 5, lane = tid & 31;
    int wm = (warp >> 2) * 32;
    int wn = (warp & 3) * 64;
    int grp = lane >> 2, tig = lane & 3;

    float acc[2][8][4];
#pragma unroll
    for (int mi = 0; mi < 2; mi++)
#pragma unroll
        for (int ni = 0; ni < 8; ni++)
#pragma unroll
            for (int q = 0; q < 4; q++) acc[mi][ni][q] = 0.f;

    GEMM_MAINLOOP(A, F, B, D, F / BK)

    int base = e * T;
#pragma unroll
    for (int mi = 0; mi < 2; mi++) {
#pragma unroll
        for (int h = 0; h < 2; h++) {
            int grow = m0 + wm + mi * 16 + grp + h * 8;
            if (grow >= cnt) continue;
            int   tokv = g_tok[base + grow];
            float wv   = g_wt [base + grow];
            float* orow = out + (size_t)tokv * D;
#pragma unroll
            for (int ni = 0; ni < 8; ni++) {
                int col = n0 + wn + ni * 8 + tig * 2;
                atomicAdd(&orow[col],     acc[mi][ni][h * 2 + 0] * wv);
                atomicAdd(&orow[col + 1], acc[mi][ni][h * 2 + 1] * wv);
            }
        }
    }
}

// ---------------- launch: per-expert pipelined streams (R12 topology) -------
extern "C" void kernel_launch(void* const* d_in, const int* in_sizes, int n_in,
                              void* d_out, int out_size) {
    const float* x  = (const float*)d_in[0];
    const float* gw = (const float*)d_in[1];
    const float* wg = (const float*)d_in[2];
    const float* wu = (const float*)d_in[3];
    const float* wd = (const float*)d_in[4];
    float* out = (float*)d_out;

    // fork converts onto side stream, serialized per expert
    cudaEventRecord(ev_fork, 0);
    cudaStreamWaitEvent(s_cv, ev_fork, 0);
    for (int e = 0; e < E; e++) {
        convert_gu_kernel<<<1024, 256, 0, s_cv>>>((const float4*)wg,
                                                  (const float4*)wu, e);
        cudaEventRecord(ev_gu[e], s_cv);
    }
    for (int e = 0; e < E; e++) {
        convert_d_kernel<<<1024, 256, 0, s_cv>>>((const float4*)wd, e);
        cudaEventRecord(ev_d[e], s_cv);
    }

    // main stream: routing prologue (concurrent with converts)
    cudaMemsetAsync(d_out, 0, (size_t)T * D * sizeof(float), 0);
    zero_cnt_kernel<<<1, 32>>>();
    router_kernel<<<T / 2, 256>>>((const float4*)x, gw);
    gather_kernel<<<dim3(T, 2), 128>>>((const float4*)x);
    cudaEventRecord(ev_route, 0);

    cudaFuncSetAttribute(gemm1_kernel,
                         cudaFuncAttributeMaxDynamicSharedMemorySize, SMEM_TOTAL);
    cudaFuncSetAttribute(gemm2_kernel,
                         cudaFuncAttributeMaxDynamicSharedMemorySize, SMEM_TOTAL);

    // per-expert pipelines: gemm1(e) -> gemm2(e)
    for (int e = 0; e < E; e++) {
        cudaStreamWaitEvent(s_e[e], ev_route, 0);
        cudaStreamWaitEvent(s_e[e], ev_gu[e], 0);
        gemm1_kernel<<<dim3(N1 / BN, T / BM), 512, SMEM_TOTAL, s_e[e]>>>(e);
        cudaStreamWaitEvent(s_e[e], ev_d[e], 0);
        gemm2_kernel<<<dim3(D / BN, T / BM), 512, SMEM_TOTAL, s_e[e]>>>(e, out);
        cudaEventRecord(ev_done[e], s_e[e]);
    }

    // join all expert streams back into the capture stream
    for (int e = 0; e < E; e++)
        cudaStreamWaitEvent(0, ev_done[e], 0);
}

// round 16
// speedup vs baseline: 1.0570x; 1.0570x over previous
#include <cuda_runtime.h>
#include <cuda_fp16.h>
#include <math.h>
#include <stdint.h>

#define T 2048
#define D 2048
#define E 8
#define F 1408
#define N1 (2 * F)   // interleaved gate/up N dimension = 2816

// ---------------- scratch (device globals; no allocation allowed) ----------
__device__ __align__(16) __half g_Wgu[(size_t)E * D * N1];  // [e][k=d][n=2f+s]
__device__ __align__(16) __half g_Wd [(size_t)E * F * D];   // [e][k=f][n=d]
__device__ __align__(16) __half g_X  [(size_t)E * T * D];   // gathered fp16 tokens
__device__ __align__(16) __half g_H  [(size_t)E * T * F];   // silu(g)*u fp16
__device__ int   g_cnt[E];
__device__ int   g_tok[E * T];
__device__ float g_wt [E * T];
__device__ int   g_dst[T * 2];

// ---------------- streams/events: created ONCE at process init -------------
static cudaStream_t s_cv, s_e[E];
static cudaEvent_t  ev_fork, ev_route, ev_gu[E], ev_d[E], ev_done[E];
static struct _StreamInit {
    _StreamInit() {
        cudaStreamCreateWithFlags(&s_cv, cudaStreamNonBlocking);
        cudaEventCreateWithFlags(&ev_fork,  cudaEventDisableTiming);
        cudaEventCreateWithFlags(&ev_route, cudaEventDisableTiming);
        for (int e = 0; e < E; e++) {
            cudaStreamCreateWithFlags(&s_e[e], cudaStreamNonBlocking);
            cudaEventCreateWithFlags(&ev_gu[e],   cudaEventDisableTiming);
            cudaEventCreateWithFlags(&ev_d[e],    cudaEventDisableTiming);
            cudaEventCreateWithFlags(&ev_done[e], cudaEventDisableTiming);
        }
    }
} _stream_init;

// ---------------- helpers ---------------------------------------------------
__global__ void zero_cnt_kernel() {
    if (threadIdx.x < E) g_cnt[threadIdx.x] = 0;
}

// per-expert gate+up convert with column interleave
__global__ void convert_gu_kernel(const float4* __restrict__ wg,
                                  const float4* __restrict__ wu, int e) {
    const int n4 = D * F / 4;
    const size_t base = (size_t)e * n4;
    uint4* dst = (uint4*)g_Wgu + base;
    const float4* sg = wg + base;
    const float4* su = wu + base;
    for (int i = blockIdx.x * blockDim.x + threadIdx.x; i < n4;
         i += gridDim.x * blockDim.x) {
        float4 g = sg[i];
        float4 u = su[i];
        __half2 h[4];
        h[0] = __floats2half2_rn(g.x, u.x);
        h[1] = __floats2half2_rn(g.y, u.y);
        h[2] = __floats2half2_rn(g.z, u.z);
        h[3] = __floats2half2_rn(g.w, u.w);
        dst[i] = *(uint4*)h;
    }
}

// per-expert down convert
__global__ void convert_d_kernel(const float4* __restrict__ wd, int e) {
    const int n4 = F * D / 4;
    const size_t base = (size_t)e * n4;
    __half2* dst = (__half2*)g_Wd + base * 2;
    const float4* src = wd + base;
    for (int i = blockIdx.x * blockDim.x + threadIdx.x; i < n4;
         i += gridDim.x * blockDim.x) {
        float4 v = src[i];
        dst[2 * i + 0] = __floats2half2_rn(v.x, v.y);
        dst[2 * i + 1] = __floats2half2_rn(v.z, v.w);
    }
}

// ---------------- router: 4 warps per token, 2 tokens per block -------------
__global__ void router_kernel(const float4* __restrict__ x4,
                              const float* __restrict__ gw) {
    __shared__ float red[2][4][E];
    int tid = threadIdx.x;
    int warp = tid >> 5, lane = tid & 31;
    int tl = warp >> 2;
    int q  = warp & 3;
    int t = blockIdx.x * 2 + tl;

    float acc[E];
#pragma unroll
    for (int e = 0; e < E; e++) acc[e] = 0.f;
    const float4* xr = x4 + (size_t)t * (D / 4) + q * (D / 16);
    const float4* gw4 = (const float4*)gw;
#pragma unroll
    for (int i = lane; i < D / 16; i += 32) {
        float4 v = xr[i];
#pragma unroll
        for (int e = 0; e < E; e++) {
            float4 g = gw4[(size_t)e * (D / 4) + q * (D / 16) + i];
            acc[e] += v.x * g.x + v.y * g.y + v.z * g.z + v.w * g.w;
        }
    }
#pragma unroll
    for (int e = 0; e < E; e++)
#pragma unroll
        for (int o = 16; o; o >>= 1)
            acc[e] += __shfl_xor_sync(0xffffffffu, acc[e], o);
    if (lane == 0)
#pragma unroll
        for (int e = 0; e < E; e++) red[tl][q][e] = acc[e];
    __syncthreads();

    if ((warp & 3) == 0 && lane == 0) {
        float l[E], m = -1e30f;
#pragma unroll
        for (int e = 0; e < E; e++) {
            l[e] = red[tl][0][e] + red[tl][1][e] + red[tl][2][e] + red[tl][3][e];
            m = fmaxf(m, l[e]);
        }
        float p[E], sum = 0.f;
#pragma unroll
        for (int e = 0; e < E; e++) { p[e] = expf(l[e] - m); sum += p[e]; }
        float inv = 1.f / sum;
#pragma unroll
        for (int e = 0; e < E; e++) p[e] *= inv;
        int i1 = 0;
#pragma unroll
        for (int e = 1; e < E; e++) if (p[e] > p[i1]) i1 = e;
        int i2 = -1;
#pragma unroll
        for (int e = 0; e < E; e++)
            if (e != i1 && (i2 < 0 || p[e] > p[i2])) i2 = e;
        int r1 = atomicAdd(&g_cnt[i1], 1);
        g_tok[i1 * T + r1] = t;  g_wt[i1 * T + r1] = p[i1];
        g_dst[t * 2 + 0] = i1 * T + r1;
        int r2 = atomicAdd(&g_cnt[i2], 1);
        g_tok[i2 * T + r2] = t;  g_wt[i2 * T + r2] = p[i2];
        g_dst[t * 2 + 1] = i2 * T + r2;
    }
}

// ---------------- gather: exact slots ---------------------------------------
__global__ void gather_kernel(const float4* __restrict__ x4) {
    int t = blockIdx.x;
    int slot = g_dst[t * 2 + blockIdx.y];
    const float4* src = x4 + (size_t)t * (D / 4);
    __half2* dst = (__half2*)(g_X + (size_t)slot * D);
    for (int i = threadIdx.x; i < D / 4; i += 128) {
        float4 v = src[i];
        dst[2 * i + 0] = __floats2half2_rn(v.x, v.y);
        dst[2 * i + 1] = __floats2half2_rn(v.z, v.w);
    }
}

// ---------------- PTX primitives --------------------------------------------
__device__ __forceinline__ unsigned smem_u32(const void* p) {
    return (unsigned)__cvta_generic_to_shared(p);
}
__device__ __forceinline__ void cp16(void* dst, const void* src) {
    asm volatile("cp.async.cg.shared.global [%0], [%1], 16;\n"
                 :: "r"(smem_u32(dst)), "l"(src));
}
__device__ __forceinline__ void cp_commit() {
    asm volatile("cp.async.commit_group;\n");
}
template <int N>
__device__ __forceinline__ void cp_wait() {
    asm volatile("cp.async.wait_group %0;\n" :: "n"(N));
}
__device__ __forceinline__ void ldsm_x4(unsigned& r0, unsigned& r1,
                                        unsigned& r2, unsigned& r3,
                                        const void* p) {
    asm volatile("ldmatrix.sync.aligned.m8n8.x4.shared.b16 {%0,%1,%2,%3}, [%4];\n"
                 : "=r"(r0), "=r"(r1), "=r"(r2), "=r"(r3) : "r"(smem_u32(p)));
}
__device__ __forceinline__ void ldsm_x4t(unsigned& r0, unsigned& r1,
                                         unsigned& r2, unsigned& r3,
                                         const void* p) {
    asm volatile("ldmatrix.sync.aligned.m8n8.x4.trans.shared.b16 {%0,%1,%2,%3}, [%4];\n"
                 : "=r"(r0), "=r"(r1), "=r"(r2), "=r"(r3) : "r"(smem_u32(p)));
}
__device__ __forceinline__ void mma16816(float* c, const unsigned* a,
                                         const unsigned* b) {
    asm volatile(
        "mma.sync.aligned.m16n8k16.row.col.f32.f16.f16.f32 "
        "{%0,%1,%2,%3}, {%4,%5,%6,%7}, {%8,%9}, {%0,%1,%2,%3};\n"
        : "+f"(c[0]), "+f"(c[1]), "+f"(c[2]), "+f"(c[3])
        : "r"(a[0]), "r"(a[1]), "r"(a[2]), "r"(a[3]), "r"(b[0]), "r"(b[1]));
}

// ---------------- tiled GEMM: 3-stage static smem, XOR swizzle (R14) --------
// A tile: 128 rows x 32 halfs = 512 x 16B chunks; phys = row*4 + (ch ^ ((row>>1)&3))
// B tile:  32 rows x 128 halfs = 512 chunks;      phys = row*16 + (ch ^ (row&7))
// Stage = 16 KB; 3 stages A+B = 49152 B = exactly the static smem limit.
#define BM 128
#define BN 128
#define BK 32

#define GEMM_LOAD_TILE(s, Aptr, ldA, Bptr, ldB, kk0)                           \
    {                                                                          \
        _Pragma("unroll")                                                      \
        for (int c = tid; c < 512; c += 256) {                                 \
            int row = c >> 2, ch = c & 3;                                      \
            cp16(&AsU[s][(row << 2) + (ch ^ ((row >> 1) & 3))],                \
                 Aptr + (size_t)row * (ldA) + (kk0) + ch * 8);                 \
        }                                                                      \
        _Pragma("unroll")                                                      \
        for (int c = tid; c < 512; c += 256) {                                 \
            int row = c >> 4, ch = c & 15;                                     \
            cp16(&BsU[s][(row << 4) + (ch ^ (row & 7))],                       \
                 Bptr + (size_t)((kk0) + row) * (ldB) + n0 + ch * 8);          \
        }                                                                      \
        cp_commit();                                                           \
    }

#define GEMM_COMPUTE_STAGE(s)                                                  \
    {                                                                          \
        _Pragma("unroll")                                                      \
        for (int ks = 0; ks < BK; ks += 16) {                                  \
            unsigned a[4][4], b[4][2];                                         \
            int l15 = lane & 15, l16 = lane >> 4;                              \
            int kch = (ks >> 3) + l16;                                         \
            _Pragma("unroll")                                                  \
            for (int mi = 0; mi < 4; mi++) {                                   \
                int row = wm + mi * 16 + l15;                                  \
                ldsm_x4(a[mi][0], a[mi][1], a[mi][2], a[mi][3],                \
                        &AsU[s][(row << 2) + (kch ^ ((row >> 1) & 3))]);       \
            }                                                                  \
            int brow = ks + l15;                                               \
            _Pragma("unroll")                                                  \
            for (int nj = 0; nj < 2; nj++) {                                   \
                int nch = ((wn + nj * 16) >> 3) + l16;                         \
                unsigned r0, r1, r2, r3;                                       \
                ldsm_x4t(r0, r1, r2, r3,                                       \
                         &BsU[s][(brow << 4) + (nch ^ (brow & 7))]);           \
                b[2 * nj][0] = r0; b[2 * nj][1] = r1;                          \
                b[2 * nj + 1][0] = r2; b[2 * nj + 1][1] = r3;                  \
            }                                                                  \
            _Pragma("unroll")                                                  \
            for (int mi = 0; mi < 4; mi++)                                     \
                _Pragma("unroll")                                              \
                for (int ni = 0; ni < 4; ni++)                                 \
                    mma16816(acc[mi][ni], a[mi], b[ni]);                       \
        }                                                                      \
    }

// 3-stage, ONE barrier per K-tile. Slot (kt+2)%3 is rewritten only after the
// iteration-kt barrier, which orders it behind compute(kt-1) (its last reader).
#define GEMM_MAINLOOP(Aptr, ldA, Bptr, ldB, NK)                                \
    GEMM_LOAD_TILE(0, Aptr, ldA, Bptr, ldB, 0)                                 \
    GEMM_LOAD_TILE(1, Aptr, ldA, Bptr, ldB, BK)                                \
    {                                                                          \
        int scur = 0;                                                          \
        for (int kt = 0; kt < (NK); kt++) {                                    \
            if (kt + 1 < (NK)) cp_wait<1>();                                   \
            else               cp_wait<0>();                                   \
            __syncthreads();                                                   \
            if (kt + 2 < (NK)) {                                               \
                int sl = scur + 2; if (sl >= 3) sl -= 3;                       \
                GEMM_LOAD_TILE(sl, Aptr, ldA, Bptr, ldB, (kt + 2) * BK)        \
            }                                                                  \
            GEMM_COMPUTE_STAGE(scur)                                           \
            scur = (scur == 2) ? 0 : scur + 1;                                 \
        }                                                                      \
    }

// ---------------- GEMM1 (per expert): H = silu(X @ Wg) * (X @ Wu) -----------
__global__ __launch_bounds__(256) void gemm1_kernel(int e) {
    int cnt = g_cnt[e];
    int m0 = blockIdx.y * BM;
    if (m0 >= cnt) return;
    int n0 = blockIdx.x * BN;

    __shared__ uint4 AsU[3][512];
    __shared__ uint4 BsU[3][512];

    const __half* A = g_X   + ((size_t)e * T + m0) * D;
    const __half* B = g_Wgu + (size_t)e * D * N1;

    int tid = threadIdx.x;
    int warp = tid >> 5, lane = tid & 31;
    int wm = (warp >> 2) * 64;
    int wn = (warp & 3) * 32;
    int grp = lane >> 2, tig = lane & 3;

    float acc[4][4][4];
#pragma unroll
    for (int mi = 0; mi < 4; mi++)
#pragma unroll
        for (int ni = 0; ni < 4; ni++)
#pragma unroll
            for (int q = 0; q < 4; q++) acc[mi][ni][q] = 0.f;

    GEMM_MAINLOOP(A, D, B, N1, D / BK)

    __half* Hp = g_H + (size_t)e * T * F;
#pragma unroll
    for (int mi = 0; mi < 4; mi++) {
#pragma unroll
        for (int h = 0; h < 2; h++) {
            int grow = m0 + wm + mi * 16 + grp + h * 8;
            if (grow >= cnt) continue;
            __half* hrow = Hp + (size_t)grow * F;
#pragma unroll
            for (int ni = 0; ni < 4; ni++) {
                int ng = n0 + wn + ni * 8;
                int f = (ng >> 1) + tig;
                float g = acc[mi][ni][h * 2 + 0];
                float u = acc[mi][ni][h * 2 + 1];
                float hv = (g / (1.f + __expf(-g))) * u;
                hrow[f] = __float2half_rn(hv);
            }
        }
    }
}

// ---------------- GEMM2 (per expert): out += wt * (H @ Wd) ------------------
__global__ __launch_bounds__(256) void gemm2_kernel(int e, float* __restrict__ out) {
    int cnt = g_cnt[e];
    int m0 = blockIdx.y * BM;
    if (m0 >= cnt) return;
    int n0 = blockIdx.x * BN;

    __shared__ uint4 AsU[3][512];
    __shared__ uint4 BsU[3][512];

    const __half* A = g_H  + ((size_t)e * T + m0) * F;
    const __half* B = g_Wd + (size_t)e * F * D;

    int tid = threadIdx.x;
    int warp = tid >> 5, lane = tid & 31;
    int wm = (warp >> 2) * 64;
    int wn = (warp & 3) * 32;
    int grp = lane >> 2, tig = lane & 3;

    float acc[4][4][4];
#pragma unroll
    for (int mi = 0; mi < 4; mi++)
#pragma unroll
        for (int ni = 0; ni < 4; ni++)
#pragma unroll
            for (int q = 0; q < 4; q++) acc[mi][ni][q] = 0.f;

    GEMM_MAINLOOP(A, F, B, D, F / BK)

    int base = e * T;
#pragma unroll
    for (int mi = 0; mi < 4; mi++) {
#pragma unroll
        for (int h = 0; h < 2; h++) {
            int grow = m0 + wm + mi * 16 + grp + h * 8;
            if (grow >= cnt) continue;
            int   tokv = g_tok[base + grow];
            float wv   = g_wt [base + grow];
            float* orow = out + (size_t)tokv * D;
#pragma unroll
            for (int ni = 0; ni < 4; ni++) {
                int col = n0 + wn + ni * 8 + tig * 2;
                atomicAdd(&orow[col],     acc[mi][ni][h * 2 + 0] * wv);
                atomicAdd(&orow[col + 1], acc[mi][ni][h * 2 + 1] * wv);
            }
        }
    }
}

// ---------------- launch: per-expert pipelined streams ----------------------
// d-converts moved to the MAIN stream (idle after gather); ev_route recorded
// BEFORE them so gemm1 streams are not gated. Graph width unchanged vs R14.
extern "C" void kernel_launch(void* const* d_in, const int* in_sizes, int n_in,
                              void* d_out, int out_size) {
    const float* x  = (const float*)d_in[0];
    const float* gw = (const float*)d_in[1];
    const float* wg = (const float*)d_in[2];
    const float* wu = (const float*)d_in[3];
    const float* wd = (const float*)d_in[4];
    float* out = (float*)d_out;

    // fork gu-converts onto side stream, serialized per expert
    cudaEventRecord(ev_fork, 0);
    cudaStreamWaitEvent(s_cv, ev_fork, 0);
    for (int e = 0; e < E; e++) {
        convert_gu_kernel<<<1024, 256, 0, s_cv>>>((const float4*)wg,
                                                  (const float4*)wu, e);
        cudaEventRecord(ev_gu[e], s_cv);
    }

    // main stream: routing prologue (concurrent with gu-converts)
    cudaMemsetAsync(d_out, 0, (size_t)T * D * sizeof(float), 0);
    zero_cnt_kernel<<<1, 32>>>();
    router_kernel<<<T / 2, 256>>>((const float4*)x, gw);
    gather_kernel<<<dim3(T, 2), 128>>>((const float4*)x);
    cudaEventRecord(ev_route, 0);

    // d-converts on the now-idle main stream: ev_d[e] ready at ~21+8e us
    for (int e = 0; e < E; e++) {
        convert_d_kernel<<<1024, 256, 0, 0>>>((const float4*)wd, e);
        cudaEventRecord(ev_d[e], 0);
    }

    // per-expert pipelines: gemm1(e) -> gemm2(e)
    for (int e = 0; e < E; e++) {
        cudaStreamWaitEvent(s_e[e], ev_route, 0);
        cudaStreamWaitEvent(s_e[e], ev_gu[e], 0);
        gemm1_kernel<<<dim3(N1 / BN, T / BM), 256, 0, s_e[e]>>>(e);
        cudaStreamWaitEvent(s_e[e], ev_d[e], 0);
        gemm2_kernel<<<dim3(D / BN, T / BM), 256, 0, s_e[e]>>>(e, out);
        cudaEventRecord(ev_done[e], s_e[e]);
    }

    // join all expert streams back into the capture stream
    for (int e = 0; e < E; e++)
        cudaStreamWaitEvent(0, ev_done[e], 0);
}

// round 17
// speedup vs baseline: 1.1253x; 1.0646x over previous
#include <cuda_runtime.h>
#include <cuda_fp16.h>
#include <math.h>
#include <stdint.h>

#define T 2048
#define D 2048
#define E 8
#define F 1408
#define N1 (2 * F)   // interleaved gate/up N dimension = 2816

// ---------------- scratch (device globals; no allocation allowed) ----------
__device__ __align__(16) __half g_Wgu[(size_t)E * D * N1];  // [e][k=d][n=2f+s]
__device__ __align__(16) __half g_Wd [(size_t)E * F * D];   // [e][k=f][n=d]
__device__ __align__(16) __half g_X  [(size_t)E * T * D];   // gathered fp16 tokens
__device__ __align__(16) __half g_H  [(size_t)E * T * F];   // silu(g)*u fp16
__device__ int   g_cnt[E];
__device__ int   g_tok[E * T];
__device__ float g_wt [E * T];

// ---------------- streams/events: created ONCE at process init -------------
static cudaStream_t s_cv, s_e[E];
static cudaEvent_t  ev_fork, ev_route, ev_gu[E], ev_d[E], ev_done[E];
static struct _StreamInit {
    _StreamInit() {
        cudaStreamCreateWithFlags(&s_cv, cudaStreamNonBlocking);
        cudaEventCreateWithFlags(&ev_fork,  cudaEventDisableTiming);
        cudaEventCreateWithFlags(&ev_route, cudaEventDisableTiming);
        for (int e = 0; e < E; e++) {
            cudaStreamCreateWithFlags(&s_e[e], cudaStreamNonBlocking);
            cudaEventCreateWithFlags(&ev_gu[e],   cudaEventDisableTiming);
            cudaEventCreateWithFlags(&ev_d[e],    cudaEventDisableTiming);
            cudaEventCreateWithFlags(&ev_done[e], cudaEventDisableTiming);
        }
    }
} _stream_init;

// ---------------- helpers ---------------------------------------------------
__global__ void zero_cnt_kernel() {
    if (threadIdx.x < E) g_cnt[threadIdx.x] = 0;
}

// per-expert gate+up convert with column interleave
__global__ void convert_gu_kernel(const float4* __restrict__ wg,
                                  const float4* __restrict__ wu, int e) {
    const int n4 = D * F / 4;
    const size_t base = (size_t)e * n4;
    uint4* dst = (uint4*)g_Wgu + base;
    const float4* sg = wg + base;
    const float4* su = wu + base;
    for (int i = blockIdx.x * blockDim.x + threadIdx.x; i < n4;
         i += gridDim.x * blockDim.x) {
        float4 g = sg[i];
        float4 u = su[i];
        __half2 h[4];
        h[0] = __floats2half2_rn(g.x, u.x);
        h[1] = __floats2half2_rn(g.y, u.y);
        h[2] = __floats2half2_rn(g.z, u.z);
        h[3] = __floats2half2_rn(g.w, u.w);
        dst[i] = *(uint4*)h;
    }
}

// per-expert down convert
__global__ void convert_d_kernel(const float4* __restrict__ wd, int e) {
    const int n4 = F * D / 4;
    const size_t base = (size_t)e * n4;
    __half2* dst = (__half2*)g_Wd + base * 2;
    const float4* src = wd + base;
    for (int i = blockIdx.x * blockDim.x + threadIdx.x; i < n4;
         i += gridDim.x * blockDim.x) {
        float4 v = src[i];
        dst[2 * i + 0] = __floats2half2_rn(v.x, v.y);
        dst[2 * i + 1] = __floats2half2_rn(v.z, v.w);
    }
}

// ---------------- fused router + gather: 2 tokens per block -----------------
__global__ void router_gather_kernel(const float4* __restrict__ x4,
                                     const float* __restrict__ gw) {
    __shared__ float red[2][4][E];
    __shared__ int   sslot[2][2];
    int tid = threadIdx.x;
    int warp = tid >> 5, lane = tid & 31;
    int tl = warp >> 2;                 // token within block (0/1)
    int q  = warp & 3;                  // quarter of D
    int t = blockIdx.x * 2 + tl;

    float acc[E];
#pragma unroll
    for (int e = 0; e < E; e++) acc[e] = 0.f;
    const float4* xr = x4 + (size_t)t * (D / 4) + q * (D / 16);
    const float4* gw4 = (const float4*)gw;
#pragma unroll
    for (int i = lane; i < D / 16; i += 32) {
        float4 v = xr[i];
#pragma unroll
        for (int e = 0; e < E; e++) {
            float4 g = gw4[(size_t)e * (D / 4) + q * (D / 16) + i];
            acc[e] += v.x * g.x + v.y * g.y + v.z * g.z + v.w * g.w;
        }
    }
#pragma unroll
    for (int e = 0; e < E; e++)
#pragma unroll
        for (int o = 16; o; o >>= 1)
            acc[e] += __shfl_xor_sync(0xffffffffu, acc[e], o);
    if (lane == 0)
#pragma unroll
        for (int e = 0; e < E; e++) red[tl][q][e] = acc[e];
    __syncthreads();

    if ((warp & 3) == 0 && lane == 0) {
        float l[E], m = -1e30f;
#pragma unroll
        for (int e = 0; e < E; e++) {
            l[e] = red[tl][0][e] + red[tl][1][e] + red[tl][2][e] + red[tl][3][e];
            m = fmaxf(m, l[e]);
        }
        float p[E], sum = 0.f;
#pragma unroll
        for (int e = 0; e < E; e++) { p[e] = expf(l[e] - m); sum += p[e]; }
        float inv = 1.f / sum;
#pragma unroll
        for (int e = 0; e < E; e++) p[e] *= inv;
        int i1 = 0;
#pragma unroll
        for (int e = 1; e < E; e++) if (p[e] > p[i1]) i1 = e;
        int i2 = -1;
#pragma unroll
        for (int e = 0; e < E; e++)
            if (e != i1 && (i2 < 0 || p[e] > p[i2])) i2 = e;
        int r1 = atomicAdd(&g_cnt[i1], 1);
        g_tok[i1 * T + r1] = t;  g_wt[i1 * T + r1] = p[i1];
        sslot[tl][0] = i1 * T + r1;
        int r2 = atomicAdd(&g_cnt[i2], 1);
        g_tok[i2 * T + r2] = t;  g_wt[i2 * T + r2] = p[i2];
        sslot[tl][1] = i2 * T + r2;
    }
    __syncthreads();

    // fused gather: 4 rows (2 tokens x 2 slots); x rows are L1/L2-hot
#pragma unroll
    for (int r = 0; r < 4; r++) {
        int tt = blockIdx.x * 2 + (r >> 1);
        int slot = sslot[r >> 1][r & 1];
        const float4* src = x4 + (size_t)tt * (D / 4);
        __half2* dst = (__half2*)(g_X + (size_t)slot * D);
        for (int i = tid; i < D / 4; i += 256) {
            float4 v = src[i];
            dst[2 * i + 0] = __floats2half2_rn(v.x, v.y);
            dst[2 * i + 1] = __floats2half2_rn(v.z, v.w);
        }
    }
}

// ---------------- PTX primitives --------------------------------------------
__device__ __forceinline__ unsigned smem_u32(const void* p) {
    return (unsigned)__cvta_generic_to_shared(p);
}
__device__ __forceinline__ void cp16(void* dst, const void* src) {
    asm volatile("cp.async.cg.shared.global [%0], [%1], 16;\n"
                 :: "r"(smem_u32(dst)), "l"(src));
}
__device__ __forceinline__ void cp_commit() {
    asm volatile("cp.async.commit_group;\n");
}
template <int N>
__device__ __forceinline__ void cp_wait() {
    asm volatile("cp.async.wait_group %0;\n" :: "n"(N));
}
__device__ __forceinline__ void ldsm_x4(unsigned& r0, unsigned& r1,
                                        unsigned& r2, unsigned& r3,
                                        const void* p) {
    asm volatile("ldmatrix.sync.aligned.m8n8.x4.shared.b16 {%0,%1,%2,%3}, [%4];\n"
                 : "=r"(r0), "=r"(r1), "=r"(r2), "=r"(r3) : "r"(smem_u32(p)));
}
__device__ __forceinline__ void ldsm_x4t(unsigned& r0, unsigned& r1,
                                         unsigned& r2, unsigned& r3,
                                         const void* p) {
    asm volatile("ldmatrix.sync.aligned.m8n8.x4.trans.shared.b16 {%0,%1,%2,%3}, [%4];\n"
                 : "=r"(r0), "=r"(r1), "=r"(r2), "=r"(r3) : "r"(smem_u32(p)));
}
__device__ __forceinline__ void mma16816(float* c, const unsigned* a,
                                         const unsigned* b) {
    asm volatile(
        "mma.sync.aligned.m16n8k16.row.col.f32.f16.f16.f32 "
        "{%0,%1,%2,%3}, {%4,%5,%6,%7}, {%8,%9}, {%0,%1,%2,%3};\n"
        : "+f"(c[0]), "+f"(c[1]), "+f"(c[2]), "+f"(c[3])
        : "r"(a[0]), "r"(a[1]), "r"(a[2]), "r"(a[3]), "r"(b[0]), "r"(b[1]));
}

// ---------------- tiled GEMM: 3-stage static smem, XOR swizzle (R14) --------
// A tile: 128 rows x 32 halfs = 512 x 16B chunks; phys = row*4 + (ch ^ ((row>>1)&3))
// B tile:  32 rows x 128 halfs = 512 chunks;      phys = row*16 + (ch ^ (row&7))
// Stage = 16 KB; 3 stages A+B = 49152 B = exactly the static smem limit.
#define BM 128
#define BN 128
#define BK 32

#define GEMM_LOAD_TILE(s, Aptr, ldA, Bptr, ldB, kk0)                           \
    {                                                                          \
        _Pragma("unroll")                                                      \
        for (int c = tid; c < 512; c += 256) {                                 \
            int row = c >> 2, ch = c & 3;                                      \
            cp16(&AsU[s][(row << 2) + (ch ^ ((row >> 1) & 3))],                \
                 Aptr + (size_t)row * (ldA) + (kk0) + ch * 8);                 \
        }                                                                      \
        _Pragma("unroll")                                                      \
        for (int c = tid; c < 512; c += 256) {                                 \
            int row = c >> 4, ch = c & 15;                                     \
            cp16(&BsU[s][(row << 4) + (ch ^ (row & 7))],                       \
                 Bptr + (size_t)((kk0) + row) * (ldB) + n0 + ch * 8);          \
        }                                                                      \
        cp_commit();                                                           \
    }

#define GEMM_COMPUTE_STAGE(s)                                                  \
    {                                                                          \
        _Pragma("unroll")                                                      \
        for (int ks = 0; ks < BK; ks += 16) {                                  \
            unsigned a[4][4], b[4][2];                                         \
            int l15 = lane & 15, l16 = lane >> 4;                              \
            int kch = (ks >> 3) + l16;                                         \
            _Pragma("unroll")                                                  \
            for (int mi = 0; mi < 4; mi++) {                                   \
                int row = wm + mi * 16 + l15;                                  \
                ldsm_x4(a[mi][0], a[mi][1], a[mi][2], a[mi][3],                \
                        &AsU[s][(row << 2) + (kch ^ ((row >> 1) & 3))]);       \
            }                                                                  \
            int brow = ks + l15;                                               \
            _Pragma("unroll")                                                  \
            for (int nj = 0; nj < 2; nj++) {                                   \
                int nch = ((wn + nj * 16) >> 3) + l16;                         \
                unsigned r0, r1, r2, r3;                                       \
                ldsm_x4t(r0, r1, r2, r3,                                       \
                         &BsU[s][(brow << 4) + (nch ^ (brow & 7))]);           \
                b[2 * nj][0] = r0; b[2 * nj][1] = r1;                          \
                b[2 * nj + 1][0] = r2; b[2 * nj + 1][1] = r3;                  \
            }                                                                  \
            _Pragma("unroll")                                                  \
            for (int mi = 0; mi < 4; mi++)                                     \
                _Pragma("unroll")                                              \
                for (int ni = 0; ni < 4; ni++)                                 \
                    mma16816(acc[mi][ni], a[mi], b[ni]);                       \
        }                                                                      \
    }

// 3-stage, ONE barrier per K-tile. Slot (kt+2)%3 is rewritten only after the
// iteration-kt barrier, which orders it behind compute(kt-1) (its last reader).
#define GEMM_MAINLOOP(Aptr, ldA, Bptr, ldB, NK)                                \
    GEMM_LOAD_TILE(0, Aptr, ldA, Bptr, ldB, 0)                                 \
    GEMM_LOAD_TILE(1, Aptr, ldA, Bptr, ldB, BK)                                \
    {                                                                          \
        int scur = 0;                                                          \
        for (int kt = 0; kt < (NK); kt++) {                                    \
            if (kt + 1 < (NK)) cp_wait<1>();                                   \
            else               cp_wait<0>();                                   \
            __syncthreads();                                                   \
            if (kt + 2 < (NK)) {                                               \
                int sl = scur + 2; if (sl >= 3) sl -= 3;                       \
                GEMM_LOAD_TILE(sl, Aptr, ldA, Bptr, ldB, (kt + 2) * BK)        \
            }                                                                  \
            GEMM_COMPUTE_STAGE(scur)                                           \
            scur = (scur == 2) ? 0 : scur + 1;                                 \
        }                                                                      \
    }

// ---------------- GEMM1 (per expert): H = silu(X @ Wg) * (X @ Wu) -----------
__global__ __launch_bounds__(256) void gemm1_kernel(int e) {
    int cnt = g_cnt[e];
    int m0 = blockIdx.y * BM;
    if (m0 >= cnt) return;
    int n0 = blockIdx.x * BN;

    __shared__ uint4 AsU[3][512];
    __shared__ uint4 BsU[3][512];

    const __half* A = g_X   + ((size_t)e * T + m0) * D;
    const __half* B = g_Wgu + (size_t)e * D * N1;

    int tid = threadIdx.x;
    int warp = tid >> 5, lane = tid & 31;
    int wm = (warp >> 2) * 64;
    int wn = (warp & 3) * 32;
    int grp = lane >> 2, tig = lane & 3;

    float acc[4][4][4];
#pragma unroll
    for (int mi = 0; mi < 4; mi++)
#pragma unroll
        for (int ni = 0; ni < 4; ni++)
#pragma unroll
            for (int q = 0; q < 4; q++) acc[mi][ni][q] = 0.f;

    GEMM_MAINLOOP(A, D, B, N1, D / BK)

    __half* Hp = g_H + (size_t)e * T * F;
#pragma unroll
    for (int mi = 0; mi < 4; mi++) {
#pragma unroll
        for (int h = 0; h < 2; h++) {
            int grow = m0 + wm + mi * 16 + grp + h * 8;
            if (grow >= cnt) continue;
            __half* hrow = Hp + (size_t)grow * F;
#pragma unroll
            for (int ni = 0; ni < 4; ni++) {
                int ng = n0 + wn + ni * 8;
                int f = (ng >> 1) + tig;
                float g = acc[mi][ni][h * 2 + 0];
                float u = acc[mi][ni][h * 2 + 1];
                float hv = (g / (1.f + __expf(-g))) * u;
                hrow[f] = __float2half_rn(hv);
            }
        }
    }
}

// ---------------- GEMM2 (per expert): out += wt * (H @ Wd) ------------------
__global__ __launch_bounds__(256) void gemm2_kernel(int e, float* __restrict__ out) {
    int cnt = g_cnt[e];
    int m0 = blockIdx.y * BM;
    if (m0 >= cnt) return;
    int n0 = blockIdx.x * BN;

    __shared__ uint4 AsU[3][512];
    __shared__ uint4 BsU[3][512];

    const __half* A = g_H  + ((size_t)e * T + m0) * F;
    const __half* B = g_Wd + (size_t)e * F * D;

    int tid = threadIdx.x;
    int warp = tid >> 5, lane = tid & 31;
    int wm = (warp >> 2) * 64;
    int wn = (warp & 3) * 32;
    int grp = lane >> 2, tig = lane & 3;

    float acc[4][4][4];
#pragma unroll
    for (int mi = 0; mi < 4; mi++)
#pragma unroll
        for (int ni = 0; ni < 4; ni++)
#pragma unroll
            for (int q = 0; q < 4; q++) acc[mi][ni][q] = 0.f;

    GEMM_MAINLOOP(A, F, B, D, F / BK)

    int base = e * T;
#pragma unroll
    for (int mi = 0; mi < 4; mi++) {
#pragma unroll
        for (int h = 0; h < 2; h++) {
            int grow = m0 + wm + mi * 16 + grp + h * 8;
            if (grow >= cnt) continue;
            int   tokv = g_tok[base + grow];
            float wv   = g_wt [base + grow];
            float* orow = out + (size_t)tokv * D;
#pragma unroll
            for (int ni = 0; ni < 4; ni++) {
                int col = n0 + wn + ni * 8 + tig * 2;
                atomicAdd(&orow[col],     acc[mi][ni][h * 2 + 0] * wv);
                atomicAdd(&orow[col + 1], acc[mi][ni][h * 2 + 1] * wv);
            }
        }
    }
}

// ---------------- launch: per-expert pipelined streams (R14 topology) -------
extern "C" void kernel_launch(void* const* d_in, const int* in_sizes, int n_in,
                              void* d_out, int out_size) {
    const float* x  = (const float*)d_in[0];
    const float* gw = (const float*)d_in[1];
    const float* wg = (const float*)d_in[2];
    const float* wu = (const float*)d_in[3];
    const float* wd = (const float*)d_in[4];
    float* out = (float*)d_out;

    // fork converts onto side stream, serialized per expert (R14 order)
    cudaEventRecord(ev_fork, 0);
    cudaStreamWaitEvent(s_cv, ev_fork, 0);
    for (int e = 0; e < E; e++) {
        convert_gu_kernel<<<2048, 256, 0, s_cv>>>((const float4*)wg,
                                                  (const float4*)wu, e);
        cudaEventRecord(ev_gu[e], s_cv);
    }
    for (int e = 0; e < E; e++) {
        convert_d_kernel<<<2048, 256, 0, s_cv>>>((const float4*)wd, e);
        cudaEventRecord(ev_d[e], s_cv);
    }

    // main stream: routing prologue (concurrent with converts)
    cudaMemsetAsync(d_out, 0, (size_t)T * D * sizeof(float), 0);
    zero_cnt_kernel<<<1, 32>>>();
    router_gather_kernel<<<T / 2, 256>>>((const float4*)x, gw);
    cudaEventRecord(ev_route, 0);

    // per-expert pipelines: gemm1(e) -> gemm2(e)
    for (int e = 0; e < E; e++) {
        cudaStreamWaitEvent(s_e[e], ev_route, 0);
        cudaStreamWaitEvent(s_e[e], ev_gu[e], 0);
        gemm1_kernel<<<dim3(N1 / BN, T / BM), 256, 0, s_e[e]>>>(e);
        cudaStreamWaitEvent(s_e[e], ev_d[e], 0);
        gemm2_kernel<<<dim3(D / BN, T / BM), 256, 0, s_e[e]>>>(e, out);
        cudaEventRecord(ev_done[e], s_e[e]);
    }

    // join all expert streams back into the capture stream
    for (int e = 0; e < E; e++)
        cudaStreamWaitEvent(0, ev_done[e], 0);
}